// round 16
// baseline (speedup 1.0000x reference)
#include <cuda_runtime.h>
#include <cuda_bf16.h>
#include <cstdint>

#define B_  32
#define T_  2048
#define D_  256
#define H_  256
#define G3_ 768
#define CH_  64                  // rec chunk length (steps)
#define NCH_ (T_ / CH_)          // 32 chunks
#define NG1_ 15                  // gemm1 M128 launches (steps 0..1919)

// Scratch (no cudaMalloc allowed)
__device__ float g_xg0[(size_t)B_ * T_ * G3_];
__device__ float g_xg1[(size_t)B_ * T_ * G3_];
__device__ float g_h1 [(size_t)B_ * T_ * H_];
// Progress counters (reset by cudaMemsetAsync at graph start)
__device__ int g_cnt_g0;            // gemm0_rest CTAs done (target 5760)
__device__ int g_rec0prog[16];      // rec0 64-step chunks done, per cluster
__device__ int g_cnt_g1[NCH_];      // xg1 ready per 64-step chunk (target 384)

typedef unsigned long long u64t;

__device__ __forceinline__ unsigned smem_u32(const void* p) {
    unsigned a;
    asm("{ .reg .u64 t; cvta.to.shared.u64 t, %1; cvt.u32.u64 %0, t; }"
        : "=r"(a) : "l"(p));
    return a;
}

// ===========================================================================
// Tensor-core GEMM (bf16 split hi/lo, 3-term), templated on M-rows per CTA
// (128 or 64). Optional device gate on rec0 progress + up to two completion
// counters.
// ===========================================================================
#define GT 256
#define KP 72
#define SM_AH 0
#define SM_AL 18432
#define SM_BH 36864
#define SM_BL 46080
#define SM_TOT 55296

__device__ __forceinline__ void mma_bf16(float& d0, float& d1, float& d2, float& d3,
                                         unsigned a0, unsigned a1, unsigned a2, unsigned a3,
                                         unsigned b0, unsigned b1) {
    asm volatile(
        "mma.sync.aligned.m16n8k16.row.col.f32.bf16.bf16.f32 "
        "{%0,%1,%2,%3}, {%4,%5,%6,%7}, {%8,%9}, {%0,%1,%2,%3};"
        : "+f"(d0), "+f"(d1), "+f"(d2), "+f"(d3)
        : "r"(a0), "r"(a1), "r"(a2), "r"(a3), "r"(b0), "r"(b1));
}

template <int MR>
__global__ void __launch_bounds__(GT)
gemm_tc_kernel(const float* __restrict__ A, const float* __restrict__ W,
               const float* __restrict__ bias, float* __restrict__ out,
               int t0, int bpb,
               const int* wait_arr, int wait_val,
               int* done_cnt, int* done_cnt2)
{
    constexpr int MWARPS = MR / 32;          // 4 (MR=128) or 2 (MR=64)
    constexpr int NWARPS = 8 / MWARPS;       // 2 or 4
    constexpr int NWTILE = 64 / NWARPS;      // 32 or 16
    constexpr int NFRAG  = NWTILE / 8;       // 4 or 2

    extern __shared__ char smem[];
    __nv_bfloat16* Ah = (__nv_bfloat16*)(smem + SM_AH);
    __nv_bfloat16* Al = (__nv_bfloat16*)(smem + SM_AL);
    __nv_bfloat16* Bh = (__nv_bfloat16*)(smem + SM_BH);
    __nv_bfloat16* Bl = (__nv_bfloat16*)(smem + SM_BL);

    const int tid  = threadIdx.x;
    const int lane = tid & 31;
    const int w    = tid >> 5;
    const int wm   = w % MWARPS;
    const int wn   = w / MWARPS;
    const int bb   = blockIdx.x / bpb;
    const size_t mrow0 = (size_t)bb * T_ + t0 + (size_t)(blockIdx.x % bpb) * MR;
    const int bn   = blockIdx.y * 64;

    if (wait_arr) {
        if (tid == 0) {
            const volatile int* p = wait_arr + (bb >> 1);
            while (*p < wait_val) {}
            __threadfence();
        }
        __syncthreads();
    }

    const int lr = lane >> 2;
    const int lc = (lane & 3) * 2;

    float d[2][NFRAG][4];
    #pragma unroll
    for (int mf = 0; mf < 2; mf++)
        #pragma unroll
        for (int nf = 0; nf < NFRAG; nf++)
            #pragma unroll
            for (int e = 0; e < 4; e++) d[mf][nf][e] = 0.f;

    for (int kb = 0; kb < 4; kb++) {
        #pragma unroll
        for (int i = 0; i < MR / 16; i++) {
            int idx = tid + i * GT;
            int row = idx >> 4;
            int c4  = (idx & 15) * 4;
            float4 v = *(const float4*)&A[(mrow0 + row) * 256 + kb * 64 + c4];
            __nv_bfloat162 h01 = __float22bfloat162_rn(make_float2(v.x, v.y));
            __nv_bfloat162 h23 = __float22bfloat162_rn(make_float2(v.z, v.w));
            float2 r01 = __bfloat1622float2(h01);
            float2 r23 = __bfloat1622float2(h23);
            __nv_bfloat162 l01 = __float22bfloat162_rn(make_float2(v.x - r01.x, v.y - r01.y));
            __nv_bfloat162 l23 = __float22bfloat162_rn(make_float2(v.z - r23.x, v.w - r23.y));
            *(__nv_bfloat162*)&Ah[row * KP + c4]     = h01;
            *(__nv_bfloat162*)&Ah[row * KP + c4 + 2] = h23;
            *(__nv_bfloat162*)&Al[row * KP + c4]     = l01;
            *(__nv_bfloat162*)&Al[row * KP + c4 + 2] = l23;
        }
        #pragma unroll
        for (int i = 0; i < 4; i++) {
            int idx = tid + i * GT;
            int row = idx >> 4;
            int c4  = (idx & 15) * 4;
            float4 v = *(const float4*)&W[(size_t)(bn + row) * 256 + kb * 64 + c4];
            __nv_bfloat162 h01 = __float22bfloat162_rn(make_float2(v.x, v.y));
            __nv_bfloat162 h23 = __float22bfloat162_rn(make_float2(v.z, v.w));
            float2 r01 = __bfloat1622float2(h01);
            float2 r23 = __bfloat1622float2(h23);
            __nv_bfloat162 l01 = __float22bfloat162_rn(make_float2(v.x - r01.x, v.y - r01.y));
            __nv_bfloat162 l23 = __float22bfloat162_rn(make_float2(v.z - r23.x, v.w - r23.y));
            *(__nv_bfloat162*)&Bh[row * KP + c4]     = h01;
            *(__nv_bfloat162*)&Bh[row * KP + c4 + 2] = h23;
            *(__nv_bfloat162*)&Bl[row * KP + c4]     = l01;
            *(__nv_bfloat162*)&Bl[row * KP + c4 + 2] = l23;
        }
        __syncthreads();

        #pragma unroll
        for (int k16 = 0; k16 < 4; k16++) {
            const int kk = k16 * 16;
            unsigned ah[2][4], al[2][4], bh[NFRAG][2], bl[NFRAG][2];
            #pragma unroll
            for (int mf = 0; mf < 2; mf++) {
                int r0 = wm * 32 + mf * 16 + lr;
                ah[mf][0] = *(const unsigned*)&Ah[r0 * KP + kk + lc];
                ah[mf][1] = *(const unsigned*)&Ah[(r0 + 8) * KP + kk + lc];
                ah[mf][2] = *(const unsigned*)&Ah[r0 * KP + kk + 8 + lc];
                ah[mf][3] = *(const unsigned*)&Ah[(r0 + 8) * KP + kk + 8 + lc];
                al[mf][0] = *(const unsigned*)&Al[r0 * KP + kk + lc];
                al[mf][1] = *(const unsigned*)&Al[(r0 + 8) * KP + kk + lc];
                al[mf][2] = *(const unsigned*)&Al[r0 * KP + kk + 8 + lc];
                al[mf][3] = *(const unsigned*)&Al[(r0 + 8) * KP + kk + 8 + lc];
            }
            #pragma unroll
            for (int nf = 0; nf < NFRAG; nf++) {
                int n0 = wn * NWTILE + nf * 8 + lr;
                bh[nf][0] = *(const unsigned*)&Bh[n0 * KP + kk + lc];
                bh[nf][1] = *(const unsigned*)&Bh[n0 * KP + kk + 8 + lc];
                bl[nf][0] = *(const unsigned*)&Bl[n0 * KP + kk + lc];
                bl[nf][1] = *(const unsigned*)&Bl[n0 * KP + kk + 8 + lc];
            }
            #pragma unroll
            for (int mf = 0; mf < 2; mf++)
                #pragma unroll
                for (int nf = 0; nf < NFRAG; nf++) {
                    float* dd = d[mf][nf];
                    mma_bf16(dd[0], dd[1], dd[2], dd[3],
                             ah[mf][0], ah[mf][1], ah[mf][2], ah[mf][3],
                             bh[nf][0], bh[nf][1]);
                    mma_bf16(dd[0], dd[1], dd[2], dd[3],
                             ah[mf][0], ah[mf][1], ah[mf][2], ah[mf][3],
                             bl[nf][0], bl[nf][1]);
                    mma_bf16(dd[0], dd[1], dd[2], dd[3],
                             al[mf][0], al[mf][1], al[mf][2], al[mf][3],
                             bh[nf][0], bh[nf][1]);
                }
        }
        __syncthreads();
    }

    #pragma unroll
    for (int mf = 0; mf < 2; mf++) {
        size_t m = mrow0 + wm * 32 + mf * 16 + lr;
        #pragma unroll
        for (int nf = 0; nf < NFRAG; nf++) {
            int n = bn + wn * NWTILE + nf * 8 + lc;
            float2 bv = *(const float2*)&bias[n];
            float2 v0 = make_float2(d[mf][nf][0] + bv.x, d[mf][nf][1] + bv.y);
            float2 v1 = make_float2(d[mf][nf][2] + bv.x, d[mf][nf][3] + bv.y);
            *(float2*)&out[m * G3_ + n]       = v0;
            *(float2*)&out[(m + 8) * G3_ + n] = v1;
        }
    }

    if (done_cnt) {
        __syncthreads();
        if (tid == 0) {
            __threadfence();
            atomicAdd(done_cnt, 1);
            if (done_cnt2) atomicAdd(done_cnt2, 1);
        }
    }
}

// ===========================================================================
// PERSISTENT recurrent kernel (64-step chunks). Same per-step math as R12+.
// ===========================================================================
#define RTHREADS 384
#define HPAD 272

__device__ __forceinline__ void st_cluster_f32(unsigned addr, unsigned rank, float v) {
    asm volatile(
        "{ .reg .b32 r; mapa.shared::cluster.u32 r, %0, %1; st.shared::cluster.f32 [r], %2; }"
        :: "r"(addr), "r"(rank), "f"(v) : "memory");
}
__device__ __forceinline__ void mbar_init(unsigned addr, unsigned count) {
    asm volatile("mbarrier.init.shared.b64 [%0], %1;" :: "r"(addr), "r"(count) : "memory");
}
__device__ __forceinline__ void mbar_arrive_peer(unsigned addr, unsigned rank) {
    asm volatile(
        "{ .reg .b32 r; mapa.shared::cluster.u32 r, %0, %1; "
        "mbarrier.arrive.release.cluster.shared::cluster.b64 _, [r]; }"
        :: "r"(addr), "r"(rank) : "memory");
}
__device__ __forceinline__ void mbar_wait_cta(unsigned addr, unsigned parity) {
    asm volatile(
        "{\n\t.reg .pred P1;\n\t"
        "WAIT_%=:\n\t"
        "mbarrier.try_wait.parity.acquire.cta.shared::cta.b64 P1, [%0], %1, 0x989680;\n\t"
        "@P1 bra DONE_%=;\n\t"
        "bra WAIT_%=;\n\t"
        "DONE_%=:\n\t}"
        :: "r"(addr), "r"(parity) : "memory");
}
__device__ __forceinline__ void cluster_barrier() {
    asm volatile("barrier.cluster.arrive.aligned;" ::: "memory");
    asm volatile("barrier.cluster.wait.aligned;"   ::: "memory");
}
__device__ __forceinline__ u64t ffma2(u64t a, u64t b, u64t c) {
    u64t d;
    asm("fma.rn.f32x2 %0, %1, %2, %3;" : "=l"(d) : "l"(a), "l"(b), "l"(c));
    return d;
}
__device__ __forceinline__ u64t add2(u64t a, u64t b) {
    u64t d;
    asm("add.rn.f32x2 %0, %1, %2;" : "=l"(d) : "l"(a), "l"(b));
    return d;
}
__device__ __forceinline__ float hsum2(u64t v) {
    float lo, hi;
    asm("mov.b64 {%0, %1}, %2;" : "=f"(lo), "=f"(hi) : "l"(v));
    return lo + hi;
}
__device__ __forceinline__ float fast_sigmoid(float x) {
    return 1.f / (1.f + __expf(-x));
}
__device__ __forceinline__ float fast_tanh(float x) {
    return 2.f / (1.f + __expf(-2.f * x)) - 1.f;
}

__global__ void __cluster_dims__(4, 1, 1) __launch_bounds__(RTHREADS, 1)
gru_rec_kernel(const float* __restrict__ xg, const float* __restrict__ Whh,
               const float* __restrict__ bhh, float* __restrict__ out,
               const int* gate_arr, int gate_target, int gate_per_chunk,
               int gate_skip, int* prog_arr)
{
    const int tid = threadIdx.x;
    const int s   = tid & 3;
    const int rg  = tid >> 2;
    const int b0  = (blockIdx.x >> 2) * 2;
    const int c   = blockIdx.x & 3;

    __shared__ __align__(16) float hb[2][2][HPAD];
    __shared__ float hgc[2][192];
    __shared__ float xgs[2][192];
    __shared__ __align__(8) unsigned long long mbar_s[2];

    u64t w2[2][32];
    #pragma unroll
    for (int q = 0; q < 2; q++) {
        int lr = rg * 2 + q;
        int g  = lr >> 6;
        int jl = lr & 63;
        const ulonglong2* wp =
            (const ulonglong2*)(Whh + (size_t)(g * 256 + c * 64 + jl) * 256 + s * 64);
        #pragma unroll
        for (int k = 0; k < 16; k++) {
            ulonglong2 v = wp[k];
            w2[q][2 * k]     = v.x;
            w2[q][2 * k + 1] = v.y;
        }
    }

    const int bt  = (tid >> 6) & 1;
    const int jl6 = tid & 63;
    const int jglob = c * 64 + jl6;
    float b_r = 0.f, b_z = 0.f, b_n = 0.f;
    if (tid < 128) {
        b_r = bhh[jglob];
        b_z = bhh[256 + jglob];
        b_n = bhh[512 + jglob];
    }
    for (int i = tid; i < 4 * HPAD; i += RTHREADS)
        ((float*)hb)[i] = 0.f;

    const unsigned mb0 = smem_u32(&mbar_s[0]);
    const unsigned mb1 = smem_u32(&mbar_s[1]);
    if (tid == 0) { mbar_init(mb0, 4); mbar_init(mb1, 4); }

    const float* xgb0 = xg + (size_t)b0 * T_ * G3_;
    const float* xgb1 = xg + (size_t)(b0 + 1) * T_ * G3_;
    const int xoff = (tid >> 6) * 256 + (tid & 63) + c * 64;
    float xgc0 = 0.f, xgc1 = 0.f;

    const int pidx = jglob + ((jglob >> 6) << 2);
    const unsigned addr0 = smem_u32(&hb[0][bt][pidx]);
    const unsigned addr1 = smem_u32(&hb[1][bt][pidx]);
    float hreg = 0.f;
    __syncthreads();
    cluster_barrier();

    int ph0 = 0, ph1 = 0;
    int cur = 0;

    for (int ci = 0; ci < NCH_; ci++) {
        if (gate_arr && (gate_per_chunk || ci >= gate_skip)) {
            if (tid == 0) {
                const volatile int* p = gate_arr + (gate_per_chunk ? ci : 0);
                while (*p < gate_target) {}
                __threadfence();
            }
            __syncthreads();
        }
        const int t0c = ci * CH_;
        if (tid < 192) {
            xgc0 = xgb0[(size_t)t0c * G3_ + xoff];
            xgc1 = xgb1[(size_t)t0c * G3_ + xoff];
        }

        for (int t = t0c; t < t0c + CH_; t++) {
            if (t > 0) {
                unsigned wa = cur ? mb1 : mb0;
                int p = cur ? ph1 : ph0;
                mbar_wait_cta(wa, p);
                if (cur) ph1 ^= 1; else ph0 ^= 1;
            }
            if (tid < 192) { xgs[0][tid] = xgc0; xgs[1][tid] = xgc1; }
            float xgn0 = 0.f, xgn1 = 0.f;
            if (tid < 192 && t + 1 < T_) {   // boundary prefetch may race; discarded
                xgn0 = xgb0[(size_t)(t + 1) * G3_ + xoff];
                xgn1 = xgb1[(size_t)(t + 1) * G3_ + xoff];
            }

            const ulonglong2* h2a = (const ulonglong2*)hb[cur][0];
            const ulonglong2* h2b = (const ulonglong2*)hb[cur][1];
            u64t p00 = 0, p01 = 0, p10 = 0, p11 = 0;
            u64t q00 = 0, q01 = 0, q10 = 0, q11 = 0;
            #pragma unroll
            for (int i = 0; i < 16; i++) {
                ulonglong2 ha = h2a[s * 17 + i];
                ulonglong2 hv = h2b[s * 17 + i];
                p00 = ffma2(w2[0][2 * i],     ha.x, p00);
                q00 = ffma2(w2[0][2 * i],     hv.x, q00);
                p01 = ffma2(w2[0][2 * i + 1], ha.y, p01);
                q01 = ffma2(w2[0][2 * i + 1], hv.y, q01);
                p10 = ffma2(w2[1][2 * i],     ha.x, p10);
                q10 = ffma2(w2[1][2 * i],     hv.x, q10);
                p11 = ffma2(w2[1][2 * i + 1], ha.y, p11);
                q11 = ffma2(w2[1][2 * i + 1], hv.y, q11);
            }
            float pa0 = hsum2(add2(p00, p01));
            float pa1 = hsum2(add2(p10, p11));
            float qa0 = hsum2(add2(q00, q01));
            float qa1 = hsum2(add2(q10, q11));
            pa0 += __shfl_xor_sync(0xffffffffu, pa0, 1);
            pa0 += __shfl_xor_sync(0xffffffffu, pa0, 2);
            pa1 += __shfl_xor_sync(0xffffffffu, pa1, 1);
            pa1 += __shfl_xor_sync(0xffffffffu, pa1, 2);
            qa0 += __shfl_xor_sync(0xffffffffu, qa0, 1);
            qa0 += __shfl_xor_sync(0xffffffffu, qa0, 2);
            qa1 += __shfl_xor_sync(0xffffffffu, qa1, 1);
            qa1 += __shfl_xor_sync(0xffffffffu, qa1, 2);
            if (s == 0) {
                hgc[0][rg * 2] = pa0; hgc[0][rg * 2 + 1] = pa1;
                hgc[1][rg * 2] = qa0; hgc[1][rg * 2 + 1] = qa1;
            }
            __syncthreads();

            if (tid < 128) {
                float hr = hgc[bt][jl6]       + b_r;
                float hz = hgc[bt][64 + jl6]  + b_z;
                float hn = hgc[bt][128 + jl6] + b_n;
                float xr = xgs[bt][jl6], xz = xgs[bt][64 + jl6], xn = xgs[bt][128 + jl6];
                float r  = fast_sigmoid(xr + hr);
                float z  = fast_sigmoid(xz + hz);
                float nn = fast_tanh(xn + r * hn);
                float hnew = (1.f - z) * nn + z * hreg;
                hreg = hnew;
                unsigned dsta = cur ? addr0 : addr1;
                #pragma unroll
                for (int p = 0; p < 4; p++) st_cluster_f32(dsta, p, hnew);
                out[((size_t)(b0 + bt) * T_ + t) * H_ + jglob] = hnew;
                asm volatile("bar.sync 3, 128;" ::: "memory");
                if (tid < 4) {
                    unsigned am = cur ? mb0 : mb1;
                    mbar_arrive_peer(am, (unsigned)tid);
                }
            }

            xgc0 = xgn0; xgc1 = xgn1;
            cur ^= 1;
        }

        if (prog_arr) {
            if (tid < 128) __threadfence();
            __syncthreads();
            cluster_barrier();
            if (c == 0 && tid == 0)
                atomicAdd(prog_arr + (blockIdx.x >> 2), 1);
        }
    }
    cluster_barrier();
}

// ---------------------------------------------------------------------------
static void launch_rec(cudaStream_t st, const float* xg, const float* Whh,
                       const float* bhh, float* out,
                       const int* gate_arr, int gate_target, int gate_per_chunk,
                       int gate_skip, int* prog_arr)
{
    cudaLaunchConfig_t cfg = {};
    cfg.gridDim  = dim3((B_ / 2) * 4, 1, 1);
    cfg.blockDim = dim3(RTHREADS, 1, 1);
    cfg.dynamicSmemBytes = 0;
    cfg.stream = st;
    cudaLaunchAttribute attrs[1];
    attrs[0].id = cudaLaunchAttributeClusterDimension;
    attrs[0].val.clusterDim.x = 4;
    attrs[0].val.clusterDim.y = 1;
    attrs[0].val.clusterDim.z = 1;
    cfg.attrs = attrs;
    cfg.numAttrs = 1;
    cudaLaunchKernelEx(&cfg, gru_rec_kernel, xg, Whh, bhh, out,
                       gate_arr, gate_target, gate_per_chunk, gate_skip, prog_arr);
}

extern "C" void kernel_launch(void* const* d_in, const int* in_sizes, int n_in,
                              void* d_out, int out_size)
{
    (void)in_sizes; (void)n_in; (void)out_size;
    const float* x   = (const float*)d_in[0];
    const float* Wih = (const float*)d_in[1];
    const float* Whh = (const float*)d_in[2];
    const float* bih = (const float*)d_in[3];
    const float* bhh = (const float*)d_in[4];
    float* out = (float*)d_out;

    float* xg0p; cudaGetSymbolAddress((void**)&xg0p, g_xg0);
    float* xg1p; cudaGetSymbolAddress((void**)&xg1p, g_xg1);
    float* h1p;  cudaGetSymbolAddress((void**)&h1p,  g_h1);
    int* cg0;  cudaGetSymbolAddress((void**)&cg0,  g_cnt_g0);
    int* rpr;  cudaGetSymbolAddress((void**)&rpr,  g_rec0prog);
    int* cg1;  cudaGetSymbolAddress((void**)&cg1,  g_cnt_g1);

    static cudaStream_t s1 = nullptr, s2 = nullptr;
    static cudaEvent_t evFork, evJoin, evJoin2, evG0;
    static bool infra_ok = false;
    if (!infra_ok) {
        cudaStreamCreateWithFlags(&s1, cudaStreamNonBlocking);
        cudaStreamCreateWithFlags(&s2, cudaStreamNonBlocking);
        cudaEventCreateWithFlags(&evFork, cudaEventDisableTiming);
        cudaEventCreateWithFlags(&evJoin, cudaEventDisableTiming);
        cudaEventCreateWithFlags(&evJoin2, cudaEventDisableTiming);
        cudaEventCreateWithFlags(&evG0, cudaEventDisableTiming);
        cudaFuncSetAttribute(gemm_tc_kernel<128>,
                             cudaFuncAttributeMaxDynamicSharedMemorySize, SM_TOT);
        cudaFuncSetAttribute(gemm_tc_kernel<64>,
                             cudaFuncAttributeMaxDynamicSharedMemorySize, SM_TOT);
        infra_ok = true;
    }

    cudaMemsetAsync(cg0, 0, sizeof(int), 0);
    cudaMemsetAsync(rpr, 0, 16 * sizeof(int), 0);
    cudaMemsetAsync(cg1, 0, NCH_ * sizeof(int), 0);

    cudaEventRecord(evFork, 0);
    cudaStreamWaitEvent(s1, evFork, 0);
    cudaStreamWaitEvent(s2, evFork, 0);

    // gemm0 for steps 0..127 on stream 0 (covers rec0 chunks 0 and 1).
    {
        dim3 gc0(B_ * 1, G3_ / 64);
        gemm_tc_kernel<128><<<gc0, GT, SM_TOT, 0>>>(x, Wih, bih, xg0p, 0, 1,
                                                    nullptr, 0, nullptr, nullptr);
    }
    // gemm0 remainder (steps 128..2047) on s2: 5760 CTAs, signals cg0.
    {
        int bpb = (T_ - 128) / 128;   // 15
        dim3 gcr(B_ * bpb, G3_ / 64);
        gemm_tc_kernel<128><<<gcr, GT, SM_TOT, s2>>>(x, Wih, bih, xg0p, 128, bpb,
                                                     nullptr, 0, cg0, nullptr);
        cudaEventRecord(evG0, s2);
    }

    // Persistent rec0 (stream 0): gated on cg0 for ci>=2; signals rpr per 64 steps.
    launch_rec(0, xg0p, Whh, bhh, h1p, cg0, 5760, 0, 2, rpr);

    // gemm1 on s2: 15 x M128 (steps 0..1919), then 2 x M64 (final 128 steps).
    const float* Wih1 = Wih + (size_t)G3_ * D_;
    const float* Whh1 = Whh + (size_t)G3_ * H_;
    const float* bih1 = bih + G3_;
    const float* bhh1 = bhh + G3_;
    for (int j = 0; j < NG1_; j++) {
        dim3 g1(B_ * 1, G3_ / 64);
        gemm_tc_kernel<128><<<g1, GT, SM_TOT, s2>>>(h1p, Wih1, bih1, xg1p,
                                                    j * 128, 1,
                                                    rpr, 2 * j + 2,
                                                    cg1 + 2 * j, cg1 + 2 * j + 1);
    }
    {
        dim3 g64(B_ * 1, G3_ / 64);
        gemm_tc_kernel<64><<<g64, GT, SM_TOT, s2>>>(h1p, Wih1, bih1, xg1p,
                                                    NG1_ * 128, 1,
                                                    rpr, 31, cg1 + 30, nullptr);
        gemm_tc_kernel<64><<<g64, GT, SM_TOT, s2>>>(h1p, Wih1, bih1, xg1p,
                                                    NG1_ * 128 + 64, 1,
                                                    rpr, 32, cg1 + 31, nullptr);
    }
    cudaEventRecord(evJoin2, s2);

    // Persistent rec1 (s1, after gemm0_rest): per-64-chunk gate on cg1[ci]>=384.
    cudaStreamWaitEvent(s1, evG0, 0);
    launch_rec(s1, xg1p, Whh1, bhh1, out, cg1, 384, 1, 0, nullptr);

    cudaEventRecord(evJoin, s1);
    cudaStreamWaitEvent(0, evJoin, 0);
    cudaStreamWaitEvent(0, evJoin2, 0);
}

// round 17
// speedup vs baseline: 1.4344x; 1.4344x over previous
#include <cuda_runtime.h>
#include <cuda_bf16.h>
#include <cstdint>

#define B_  32
#define T_  2048
#define D_  256
#define H_  256
#define G3_ 768
#define CH_  128                 // chunk length (steps)
#define NCH_ (T_ / CH_)          // 16 chunks

// Scratch (no cudaMalloc allowed)
__device__ float g_xg0[(size_t)B_ * T_ * G3_];
__device__ float g_xg1[(size_t)B_ * T_ * G3_];
__device__ float g_h1 [(size_t)B_ * T_ * H_];
// Progress counters (reset by cudaMemsetAsync at graph start each replay)
__device__ int g_cnt_g0;            // gemm0_rest CTAs done (target 5760)
__device__ int g_rec0prog[16];      // rec0 chunks done, per cluster
__device__ int g_cnt_g1[NCH_];      // gemm1 chunk i CTAs done (target 384)

typedef unsigned long long u64t;

__device__ __forceinline__ unsigned smem_u32(const void* p) {
    unsigned a;
    asm("{ .reg .u64 t; cvta.to.shared.u64 t, %1; cvt.u32.u64 %0, t; }"
        : "=r"(a) : "l"(p));
    return a;
}

// ===========================================================================
// Tensor-core GEMM (bf16 split hi/lo, 3-term) + optional device-side gate
// (spin on rec0 progress) and completion counter.   [R14 version]
// ===========================================================================
#define GT 256
#define KP 72
#define SM_AH 0
#define SM_AL 18432
#define SM_BH 36864
#define SM_BL 46080
#define SM_TOT 55296

__device__ __forceinline__ void mma_bf16(float& d0, float& d1, float& d2, float& d3,
                                         unsigned a0, unsigned a1, unsigned a2, unsigned a3,
                                         unsigned b0, unsigned b1) {
    asm volatile(
        "mma.sync.aligned.m16n8k16.row.col.f32.bf16.bf16.f32 "
        "{%0,%1,%2,%3}, {%4,%5,%6,%7}, {%8,%9}, {%0,%1,%2,%3};"
        : "+f"(d0), "+f"(d1), "+f"(d2), "+f"(d3)
        : "r"(a0), "r"(a1), "r"(a2), "r"(a3), "r"(b0), "r"(b1));
}

__global__ void __launch_bounds__(GT)
gemm_tc_kernel(const float* __restrict__ A, const float* __restrict__ W,
               const float* __restrict__ bias, float* __restrict__ out,
               int t0, int bpb,
               const int* wait_arr, int wait_val, int* done_cnt)
{
    extern __shared__ char smem[];
    __nv_bfloat16* Ah = (__nv_bfloat16*)(smem + SM_AH);
    __nv_bfloat16* Al = (__nv_bfloat16*)(smem + SM_AL);
    __nv_bfloat16* Bh = (__nv_bfloat16*)(smem + SM_BH);
    __nv_bfloat16* Bl = (__nv_bfloat16*)(smem + SM_BL);

    const int tid  = threadIdx.x;
    const int lane = tid & 31;
    const int w    = tid >> 5;
    const int wm   = w & 3;
    const int wn   = w >> 2;
    const int bb   = blockIdx.x / bpb;
    const size_t mrow0 = (size_t)bb * T_ + t0 + (size_t)(blockIdx.x % bpb) * 128;
    const int bn   = blockIdx.y * 64;

    if (wait_arr) {
        if (tid == 0) {
            const volatile int* p = wait_arr + (bb >> 1);
            while (*p < wait_val) {}
            __threadfence();
        }
        __syncthreads();
    }

    const int lr = lane >> 2;
    const int lc = (lane & 3) * 2;

    float d[2][4][4];
    #pragma unroll
    for (int mf = 0; mf < 2; mf++)
        #pragma unroll
        for (int nf = 0; nf < 4; nf++)
            #pragma unroll
            for (int e = 0; e < 4; e++) d[mf][nf][e] = 0.f;

    for (int kb = 0; kb < 4; kb++) {
        #pragma unroll
        for (int i = 0; i < 8; i++) {
            int idx = tid + i * GT;
            int row = idx >> 4;
            int c4  = (idx & 15) * 4;
            float4 v = *(const float4*)&A[(mrow0 + row) * 256 + kb * 64 + c4];
            __nv_bfloat162 h01 = __float22bfloat162_rn(make_float2(v.x, v.y));
            __nv_bfloat162 h23 = __float22bfloat162_rn(make_float2(v.z, v.w));
            float2 r01 = __bfloat1622float2(h01);
            float2 r23 = __bfloat1622float2(h23);
            __nv_bfloat162 l01 = __float22bfloat162_rn(make_float2(v.x - r01.x, v.y - r01.y));
            __nv_bfloat162 l23 = __float22bfloat162_rn(make_float2(v.z - r23.x, v.w - r23.y));
            *(__nv_bfloat162*)&Ah[row * KP + c4]     = h01;
            *(__nv_bfloat162*)&Ah[row * KP + c4 + 2] = h23;
            *(__nv_bfloat162*)&Al[row * KP + c4]     = l01;
            *(__nv_bfloat162*)&Al[row * KP + c4 + 2] = l23;
        }
        #pragma unroll
        for (int i = 0; i < 4; i++) {
            int idx = tid + i * GT;
            int row = idx >> 4;
            int c4  = (idx & 15) * 4;
            float4 v = *(const float4*)&W[(size_t)(bn + row) * 256 + kb * 64 + c4];
            __nv_bfloat162 h01 = __float22bfloat162_rn(make_float2(v.x, v.y));
            __nv_bfloat162 h23 = __float22bfloat162_rn(make_float2(v.z, v.w));
            float2 r01 = __bfloat1622float2(h01);
            float2 r23 = __bfloat1622float2(h23);
            __nv_bfloat162 l01 = __float22bfloat162_rn(make_float2(v.x - r01.x, v.y - r01.y));
            __nv_bfloat162 l23 = __float22bfloat162_rn(make_float2(v.z - r23.x, v.w - r23.y));
            *(__nv_bfloat162*)&Bh[row * KP + c4]     = h01;
            *(__nv_bfloat162*)&Bh[row * KP + c4 + 2] = h23;
            *(__nv_bfloat162*)&Bl[row * KP + c4]     = l01;
            *(__nv_bfloat162*)&Bl[row * KP + c4 + 2] = l23;
        }
        __syncthreads();

        #pragma unroll
        for (int k16 = 0; k16 < 4; k16++) {
            const int kk = k16 * 16;
            unsigned ah[2][4], al[2][4], bh[4][2], bl[4][2];
            #pragma unroll
            for (int mf = 0; mf < 2; mf++) {
                int r0 = wm * 32 + mf * 16 + lr;
                ah[mf][0] = *(const unsigned*)&Ah[r0 * KP + kk + lc];
                ah[mf][1] = *(const unsigned*)&Ah[(r0 + 8) * KP + kk + lc];
                ah[mf][2] = *(const unsigned*)&Ah[r0 * KP + kk + 8 + lc];
                ah[mf][3] = *(const unsigned*)&Ah[(r0 + 8) * KP + kk + 8 + lc];
                al[mf][0] = *(const unsigned*)&Al[r0 * KP + kk + lc];
                al[mf][1] = *(const unsigned*)&Al[(r0 + 8) * KP + kk + lc];
                al[mf][2] = *(const unsigned*)&Al[r0 * KP + kk + 8 + lc];
                al[mf][3] = *(const unsigned*)&Al[(r0 + 8) * KP + kk + 8 + lc];
            }
            #pragma unroll
            for (int nf = 0; nf < 4; nf++) {
                int n0 = wn * 32 + nf * 8 + lr;
                bh[nf][0] = *(const unsigned*)&Bh[n0 * KP + kk + lc];
                bh[nf][1] = *(const unsigned*)&Bh[n0 * KP + kk + 8 + lc];
                bl[nf][0] = *(const unsigned*)&Bl[n0 * KP + kk + lc];
                bl[nf][1] = *(const unsigned*)&Bl[n0 * KP + kk + 8 + lc];
            }
            #pragma unroll
            for (int mf = 0; mf < 2; mf++)
                #pragma unroll
                for (int nf = 0; nf < 4; nf++) {
                    float* dd = d[mf][nf];
                    mma_bf16(dd[0], dd[1], dd[2], dd[3],
                             ah[mf][0], ah[mf][1], ah[mf][2], ah[mf][3],
                             bh[nf][0], bh[nf][1]);
                    mma_bf16(dd[0], dd[1], dd[2], dd[3],
                             ah[mf][0], ah[mf][1], ah[mf][2], ah[mf][3],
                             bl[nf][0], bl[nf][1]);
                    mma_bf16(dd[0], dd[1], dd[2], dd[3],
                             al[mf][0], al[mf][1], al[mf][2], al[mf][3],
                             bh[nf][0], bh[nf][1]);
                }
        }
        __syncthreads();
    }

    #pragma unroll
    for (int mf = 0; mf < 2; mf++) {
        size_t m = mrow0 + wm * 32 + mf * 16 + lr;
        #pragma unroll
        for (int nf = 0; nf < 4; nf++) {
            int n = bn + wn * 32 + nf * 8 + lc;
            float2 bv = *(const float2*)&bias[n];
            float2 v0 = make_float2(d[mf][nf][0] + bv.x, d[mf][nf][1] + bv.y);
            float2 v1 = make_float2(d[mf][nf][2] + bv.x, d[mf][nf][3] + bv.y);
            *(float2*)&out[m * G3_ + n]       = v0;
            *(float2*)&out[(m + 8) * G3_ + n] = v1;
        }
    }

    if (done_cnt) {
        __syncthreads();
        if (tid == 0) { __threadfence(); atomicAdd(done_cnt, 1); }
    }
}

// ===========================================================================
// PERSISTENT recurrent kernel (128-step chunks) — R14 version with ONE
// change: out[] store + next-step xg prefetch moved AFTER the mbar arrives
// (off the inter-CTA critical path).
// ===========================================================================
#define RTHREADS 384
#define HPAD 272

__device__ __forceinline__ void st_cluster_f32(unsigned addr, unsigned rank, float v) {
    asm volatile(
        "{ .reg .b32 r; mapa.shared::cluster.u32 r, %0, %1; st.shared::cluster.f32 [r], %2; }"
        :: "r"(addr), "r"(rank), "f"(v) : "memory");
}
__device__ __forceinline__ void mbar_init(unsigned addr, unsigned count) {
    asm volatile("mbarrier.init.shared.b64 [%0], %1;" :: "r"(addr), "r"(count) : "memory");
}
__device__ __forceinline__ void mbar_arrive_peer(unsigned addr, unsigned rank) {
    asm volatile(
        "{ .reg .b32 r; mapa.shared::cluster.u32 r, %0, %1; "
        "mbarrier.arrive.release.cluster.shared::cluster.b64 _, [r]; }"
        :: "r"(addr), "r"(rank) : "memory");
}
__device__ __forceinline__ void mbar_wait_cta(unsigned addr, unsigned parity) {
    asm volatile(
        "{\n\t.reg .pred P1;\n\t"
        "WAIT_%=:\n\t"
        "mbarrier.try_wait.parity.acquire.cta.shared::cta.b64 P1, [%0], %1, 0x989680;\n\t"
        "@P1 bra DONE_%=;\n\t"
        "bra WAIT_%=;\n\t"
        "DONE_%=:\n\t}"
        :: "r"(addr), "r"(parity) : "memory");
}
__device__ __forceinline__ void cluster_barrier() {
    asm volatile("barrier.cluster.arrive.aligned;" ::: "memory");
    asm volatile("barrier.cluster.wait.aligned;"   ::: "memory");
}
__device__ __forceinline__ u64t ffma2(u64t a, u64t b, u64t c) {
    u64t d;
    asm("fma.rn.f32x2 %0, %1, %2, %3;" : "=l"(d) : "l"(a), "l"(b), "l"(c));
    return d;
}
__device__ __forceinline__ u64t add2(u64t a, u64t b) {
    u64t d;
    asm("add.rn.f32x2 %0, %1, %2;" : "=l"(d) : "l"(a), "l"(b));
    return d;
}
__device__ __forceinline__ float hsum2(u64t v) {
    float lo, hi;
    asm("mov.b64 {%0, %1}, %2;" : "=f"(lo), "=f"(hi) : "l"(v));
    return lo + hi;
}
__device__ __forceinline__ float fast_sigmoid(float x) {
    return 1.f / (1.f + __expf(-x));
}
__device__ __forceinline__ float fast_tanh(float x) {
    return 2.f / (1.f + __expf(-2.f * x)) - 1.f;
}

__global__ void __cluster_dims__(4, 1, 1) __launch_bounds__(RTHREADS, 1)
gru_rec_kernel(const float* __restrict__ xg, const float* __restrict__ Whh,
               const float* __restrict__ bhh, float* __restrict__ out,
               const int* gate_arr, int gate_target, int gate_per_chunk,
               int* prog_arr)
{
    const int tid = threadIdx.x;
    const int s   = tid & 3;
    const int rg  = tid >> 2;
    const int b0  = (blockIdx.x >> 2) * 2;
    const int c   = blockIdx.x & 3;

    __shared__ __align__(16) float hb[2][2][HPAD];
    __shared__ float hgc[2][192];
    __shared__ float xgs[2][192];
    __shared__ __align__(8) unsigned long long mbar_s[2];

    u64t w2[2][32];
    #pragma unroll
    for (int q = 0; q < 2; q++) {
        int lr = rg * 2 + q;
        int g  = lr >> 6;
        int jl = lr & 63;
        const ulonglong2* wp =
            (const ulonglong2*)(Whh + (size_t)(g * 256 + c * 64 + jl) * 256 + s * 64);
        #pragma unroll
        for (int k = 0; k < 16; k++) {
            ulonglong2 v = wp[k];
            w2[q][2 * k]     = v.x;
            w2[q][2 * k + 1] = v.y;
        }
    }

    const int bt  = (tid >> 6) & 1;
    const int jl6 = tid & 63;
    const int jglob = c * 64 + jl6;
    float b_r = 0.f, b_z = 0.f, b_n = 0.f;
    if (tid < 128) {
        b_r = bhh[jglob];
        b_z = bhh[256 + jglob];
        b_n = bhh[512 + jglob];
    }
    for (int i = tid; i < 4 * HPAD; i += RTHREADS)
        ((float*)hb)[i] = 0.f;

    const unsigned mb0 = smem_u32(&mbar_s[0]);
    const unsigned mb1 = smem_u32(&mbar_s[1]);
    if (tid == 0) { mbar_init(mb0, 4); mbar_init(mb1, 4); }

    const float* xgb0 = xg + (size_t)b0 * T_ * G3_;
    const float* xgb1 = xg + (size_t)(b0 + 1) * T_ * G3_;
    const int xoff = (tid >> 6) * 256 + (tid & 63) + c * 64;
    float xgc0 = 0.f, xgc1 = 0.f;

    const int pidx = jglob + ((jglob >> 6) << 2);
    const unsigned addr0 = smem_u32(&hb[0][bt][pidx]);
    const unsigned addr1 = smem_u32(&hb[1][bt][pidx]);
    float hreg = 0.f;
    __syncthreads();
    cluster_barrier();

    int ph0 = 0, ph1 = 0;
    int cur = 0;

    for (int ci = 0; ci < NCH_; ci++) {
        if (gate_arr && (gate_per_chunk || ci > 0)) {
            if (tid == 0) {
                const volatile int* p = gate_arr + (gate_per_chunk ? ci : 0);
                while (*p < gate_target) {}
                __threadfence();
            }
            __syncthreads();
        }
        const int t0c = ci * CH_;
        if (tid < 192) {
            xgc0 = xgb0[(size_t)t0c * G3_ + xoff];
            xgc1 = xgb1[(size_t)t0c * G3_ + xoff];
        }

        for (int t = t0c; t < t0c + CH_; t++) {
            if (t > 0) {
                unsigned wa = cur ? mb1 : mb0;
                int p = cur ? ph1 : ph0;
                mbar_wait_cta(wa, p);
                if (cur) ph1 ^= 1; else ph0 ^= 1;
            }
            if (tid < 192) { xgs[0][tid] = xgc0; xgs[1][tid] = xgc1; }
            float xgn0 = 0.f, xgn1 = 0.f;
            if (tid >= 128 && tid < 192 && t + 1 < T_) {   // non-gate lanes prefetch here
                xgn0 = xgb0[(size_t)(t + 1) * G3_ + xoff];
                xgn1 = xgb1[(size_t)(t + 1) * G3_ + xoff];
            }

            const ulonglong2* h2a = (const ulonglong2*)hb[cur][0];
            const ulonglong2* h2b = (const ulonglong2*)hb[cur][1];
            u64t p00 = 0, p01 = 0, p10 = 0, p11 = 0;
            u64t q00 = 0, q01 = 0, q10 = 0, q11 = 0;
            #pragma unroll
            for (int i = 0; i < 16; i++) {
                ulonglong2 ha = h2a[s * 17 + i];
                ulonglong2 hv = h2b[s * 17 + i];
                p00 = ffma2(w2[0][2 * i],     ha.x, p00);
                q00 = ffma2(w2[0][2 * i],     hv.x, q00);
                p01 = ffma2(w2[0][2 * i + 1], ha.y, p01);
                q01 = ffma2(w2[0][2 * i + 1], hv.y, q01);
                p10 = ffma2(w2[1][2 * i],     ha.x, p10);
                q10 = ffma2(w2[1][2 * i],     hv.x, q10);
                p11 = ffma2(w2[1][2 * i + 1], ha.y, p11);
                q11 = ffma2(w2[1][2 * i + 1], hv.y, q11);
            }
            float pa0 = hsum2(add2(p00, p01));
            float pa1 = hsum2(add2(p10, p11));
            float qa0 = hsum2(add2(q00, q01));
            float qa1 = hsum2(add2(q10, q11));
            pa0 += __shfl_xor_sync(0xffffffffu, pa0, 1);
            pa0 += __shfl_xor_sync(0xffffffffu, pa0, 2);
            pa1 += __shfl_xor_sync(0xffffffffu, pa1, 1);
            pa1 += __shfl_xor_sync(0xffffffffu, pa1, 2);
            qa0 += __shfl_xor_sync(0xffffffffu, qa0, 1);
            qa0 += __shfl_xor_sync(0xffffffffu, qa0, 2);
            qa1 += __shfl_xor_sync(0xffffffffu, qa1, 1);
            qa1 += __shfl_xor_sync(0xffffffffu, qa1, 2);
            if (s == 0) {
                hgc[0][rg * 2] = pa0; hgc[0][rg * 2 + 1] = pa1;
                hgc[1][rg * 2] = qa0; hgc[1][rg * 2 + 1] = qa1;
            }
            __syncthreads();

            if (tid < 128) {
                float hr = hgc[bt][jl6]       + b_r;
                float hz = hgc[bt][64 + jl6]  + b_z;
                float hn = hgc[bt][128 + jl6] + b_n;
                float xr = xgs[bt][jl6], xz = xgs[bt][64 + jl6], xn = xgs[bt][128 + jl6];
                float r  = fast_sigmoid(xr + hr);
                float z  = fast_sigmoid(xz + hz);
                float nn = fast_tanh(xn + r * hn);
                float hnew = (1.f - z) * nn + z * hreg;
                hreg = hnew;
                unsigned dsta = cur ? addr0 : addr1;
                #pragma unroll
                for (int p = 0; p < 4; p++) st_cluster_f32(dsta, p, hnew);
                asm volatile("bar.sync 3, 128;" ::: "memory");
                if (tid < 4) {
                    unsigned am = cur ? mb0 : mb1;
                    mbar_arrive_peer(am, (unsigned)tid);
                }
                // OFF the inter-CTA critical path: output store + xg prefetch
                out[((size_t)(b0 + bt) * T_ + t) * H_ + jglob] = hnew;
                if (t + 1 < T_) {
                    xgn0 = xgb0[(size_t)(t + 1) * G3_ + xoff];
                    xgn1 = xgb1[(size_t)(t + 1) * G3_ + xoff];
                }
            }

            xgc0 = xgn0; xgc1 = xgn1;
            cur ^= 1;
        }

        if (prog_arr) {
            if (tid < 128) __threadfence();
            __syncthreads();
            cluster_barrier();
            if (c == 0 && tid == 0)
                atomicAdd(prog_arr + (blockIdx.x >> 2), 1);
        }
    }
    cluster_barrier();
}

// ---------------------------------------------------------------------------
static void launch_rec(cudaStream_t st, const float* xg, const float* Whh,
                       const float* bhh, float* out,
                       const int* gate_arr, int gate_target, int gate_per_chunk,
                       int* prog_arr)
{
    cudaLaunchConfig_t cfg = {};
    cfg.gridDim  = dim3((B_ / 2) * 4, 1, 1);
    cfg.blockDim = dim3(RTHREADS, 1, 1);
    cfg.dynamicSmemBytes = 0;
    cfg.stream = st;
    cudaLaunchAttribute attrs[1];
    attrs[0].id = cudaLaunchAttributeClusterDimension;
    attrs[0].val.clusterDim.x = 4;
    attrs[0].val.clusterDim.y = 1;
    attrs[0].val.clusterDim.z = 1;
    cfg.attrs = attrs;
    cfg.numAttrs = 1;
    cudaLaunchKernelEx(&cfg, gru_rec_kernel, xg, Whh, bhh, out,
                       gate_arr, gate_target, gate_per_chunk, prog_arr);
}

extern "C" void kernel_launch(void* const* d_in, const int* in_sizes, int n_in,
                              void* d_out, int out_size)
{
    (void)in_sizes; (void)n_in; (void)out_size;
    const float* x   = (const float*)d_in[0];
    const float* Wih = (const float*)d_in[1];
    const float* Whh = (const float*)d_in[2];
    const float* bih = (const float*)d_in[3];
    const float* bhh = (const float*)d_in[4];
    float* out = (float*)d_out;

    float* xg0p; cudaGetSymbolAddress((void**)&xg0p, g_xg0);
    float* xg1p; cudaGetSymbolAddress((void**)&xg1p, g_xg1);
    float* h1p;  cudaGetSymbolAddress((void**)&h1p,  g_h1);
    int* cg0;  cudaGetSymbolAddress((void**)&cg0,  g_cnt_g0);
    int* rpr;  cudaGetSymbolAddress((void**)&rpr,  g_rec0prog);
    int* cg1;  cudaGetSymbolAddress((void**)&cg1,  g_cnt_g1);

    static cudaStream_t s1 = nullptr, s2 = nullptr;
    static cudaEvent_t evFork, evJoin, evJoin2, evG0;
    static bool infra_ok = false;
    if (!infra_ok) {
        cudaStreamCreateWithFlags(&s1, cudaStreamNonBlocking);
        cudaStreamCreateWithFlags(&s2, cudaStreamNonBlocking);
        cudaEventCreateWithFlags(&evFork, cudaEventDisableTiming);
        cudaEventCreateWithFlags(&evJoin, cudaEventDisableTiming);
        cudaEventCreateWithFlags(&evJoin2, cudaEventDisableTiming);
        cudaEventCreateWithFlags(&evG0, cudaEventDisableTiming);
        cudaFuncSetAttribute(gemm_tc_kernel,
                             cudaFuncAttributeMaxDynamicSharedMemorySize, SM_TOT);
        infra_ok = true;
    }

    cudaMemsetAsync(cg0, 0, sizeof(int), 0);
    cudaMemsetAsync(rpr, 0, 16 * sizeof(int), 0);
    cudaMemsetAsync(cg1, 0, NCH_ * sizeof(int), 0);

    cudaEventRecord(evFork, 0);
    cudaStreamWaitEvent(s1, evFork, 0);
    cudaStreamWaitEvent(s2, evFork, 0);

    // gemm0 chunk 0 on stream 0 (rec0 needs it immediately; stream-ordered).
    {
        dim3 gc0(B_ * (CH_ / 128), G3_ / 64);
        gemm_tc_kernel<<<gc0, GT, SM_TOT, 0>>>(x, Wih, bih, xg0p, 0, CH_ / 128,
                                               nullptr, 0, nullptr);
    }
    // gemm0 remainder on s2 (5760 CTAs), signals g_cnt_g0.
    {
        int bpb = (T_ - CH_) / 128;
        dim3 gcr(B_ * bpb, G3_ / 64);
        gemm_tc_kernel<<<gcr, GT, SM_TOT, s2>>>(x, Wih, bih, xg0p, CH_, bpb,
                                                nullptr, 0, cg0);
        cudaEventRecord(evG0, s2);
    }

    // Persistent rec0 (stream 0): gated on g_cnt_g0 for ci>=1; signals rpr.
    launch_rec(0, xg0p, Whh, bhh, h1p, cg0, 5760, 0, rpr);

    // gemm1 chunk kernels on s2 (in order after gemm0_rest).
    const float* Wih1 = Wih + (size_t)G3_ * D_;
    const float* Whh1 = Whh + (size_t)G3_ * H_;
    const float* bih1 = bih + G3_;
    const float* bhh1 = bhh + G3_;
    for (int i = 0; i < NCH_; i++) {
        dim3 g1(B_ * (CH_ / 128), G3_ / 64);
        gemm_tc_kernel<<<g1, GT, SM_TOT, s2>>>(h1p, Wih1, bih1, xg1p,
                                               i * CH_, CH_ / 128,
                                               rpr, i + 1, cg1 + i);
    }
    cudaEventRecord(evJoin2, s2);

    // Persistent rec1 (s1, after gemm0_rest): per-chunk gate on g_cnt_g1[ci].
    cudaStreamWaitEvent(s1, evG0, 0);
    launch_rec(s1, xg1p, Whh1, bhh1, out, cg1, 384, 1, nullptr);

    cudaEventRecord(evJoin, s1);
    cudaStreamWaitEvent(0, evJoin, 0);
    cudaStreamWaitEvent(0, evJoin2, 0);
}